// round 1
// baseline (speedup 1.0000x reference)
#include <cuda_runtime.h>

// LightGCN: 3-layer normalized-adjacency propagation.
//   deg[s]  = #edges with src==s  (duplicates count)
//   dinv    = deg^-0.5 (0 if deg==0)
//   x_{k+1}[s] = sum_e dinv[s]*dinv[dst(e)] * x_k[dst(e)]   (e: src(e)==s)
//   out = (emb + x1 + x2 + x3) / 4
//
// Strategy: build CSR per launch (histogram -> scan -> scatter), then 3
// warp-per-row gather SpMM kernels. Feature matrix (76.8MB) fits in L2.

#define D 128                 // feature dim (float4 x 32 lanes)
#define MAX_NODES 160000
#define MAX_EDGES 2200000
#define SCAN_BLK 1024

__device__ int   g_deg[MAX_NODES];
__device__ int   g_rowptr[MAX_NODES + 1];
__device__ int   g_cursor[MAX_NODES];
__device__ float g_dinv[MAX_NODES];
__device__ int   g_cols[MAX_EDGES];
__device__ float g_x0[(size_t)MAX_NODES * D];
__device__ float g_x1[(size_t)MAX_NODES * D];
__device__ int   g_bsum[256];
__device__ int   g_bpre[256];
__device__ int   g_total;

// ---------------------------------------------------------------- setup ----

__global__ void zero_deg_kernel(int n) {
    int i = blockIdx.x * blockDim.x + threadIdx.x;
    if (i < n) g_deg[i] = 0;
}

__global__ void hist_kernel(const int* __restrict__ src, int nE) {
    int e = blockIdx.x * blockDim.x + threadIdx.x;
    if (e < nE) atomicAdd(&g_deg[src[e]], 1);
}

// exclusive scan of g_deg into g_rowptr (per-block), block sums to g_bsum
__global__ void scan1_kernel(int n) {
    __shared__ int sh[SCAN_BLK];
    int tid = threadIdx.x;
    int i = blockIdx.x * SCAN_BLK + tid;
    int v = (i < n) ? g_deg[i] : 0;
    sh[tid] = v;
    __syncthreads();
    for (int off = 1; off < SCAN_BLK; off <<= 1) {
        int t = (tid >= off) ? sh[tid - off] : 0;
        __syncthreads();
        sh[tid] += t;
        __syncthreads();
    }
    if (i < n) g_rowptr[i] = sh[tid] - v;      // exclusive within block
    if (tid == SCAN_BLK - 1) g_bsum[blockIdx.x] = sh[tid];
}

// single-block scan of block sums (nb <= 256)
__global__ void scan2_kernel(int nb) {
    __shared__ int sh[256];
    int tid = threadIdx.x;
    int v = (tid < nb) ? g_bsum[tid] : 0;
    sh[tid] = v;
    __syncthreads();
    for (int off = 1; off < 256; off <<= 1) {
        int t = (tid >= off) ? sh[tid - off] : 0;
        __syncthreads();
        sh[tid] += t;
        __syncthreads();
    }
    if (tid < nb) g_bpre[tid] = sh[tid] - v;   // exclusive block prefix
    if (tid == 255) g_total = sh[255];         // grand total (= nE)
}

// add block prefixes; init cursors; compute dinv
__global__ void scan3_kernel(int n) {
    int i = blockIdx.x * blockDim.x + threadIdx.x;
    if (i < n) {
        int rp = g_rowptr[i] + g_bpre[i >> 10];
        g_rowptr[i] = rp;
        g_cursor[i] = rp;
        int d = g_deg[i];
        g_dinv[i] = (d > 0) ? rsqrtf((float)d) : 0.0f;
    }
    if (i == 0) g_rowptr[n] = g_total;
}

__global__ void scatter_kernel(const int* __restrict__ src,
                               const int* __restrict__ dst, int nE) {
    int e = blockIdx.x * blockDim.x + threadIdx.x;
    if (e < nE) {
        int s = src[e];
        int pos = atomicAdd(&g_cursor[s], 1);
        g_cols[pos] = dst[e];
    }
}

// ----------------------------------------------------------------- SpMM ----
// One warp per row. Each lane holds one float4 (D=128 floats = 32 lanes x 4).
// layer 0: gather from (user_w, item_w) split; write x0; acc = emb + res
// layer 1: gather from x0; write x1; acc += res
// layer 2: gather from x1; acc = (acc + res) * 0.25

__global__ void __launch_bounds__(256)
spmm_kernel(const float* __restrict__ uw, const float* __restrict__ iw,
            int num_users, int n_nodes, float* __restrict__ acc, int layer) {
    int warp = (blockIdx.x * blockDim.x + threadIdx.x) >> 5;
    int lane = threadIdx.x & 31;
    if (warp >= n_nodes) return;
    int row = warp;

    const float *xu, *xi;
    int split;
    float* xout;
    if (layer == 0)      { xu = uw;   xi = iw;   split = num_users; xout = g_x0; }
    else if (layer == 1) { xu = g_x0; xi = g_x0; split = n_nodes;   xout = g_x1; }
    else                 { xu = g_x1; xi = g_x1; split = n_nodes;   xout = nullptr; }

    float dr = g_dinv[row];
    int start = g_rowptr[row];
    int end   = g_rowptr[row + 1];

    float4 a = make_float4(0.f, 0.f, 0.f, 0.f);
    int j = start;
    // 2-way unrolled for MLP
    for (; j + 1 < end; j += 2) {
        int c0 = __ldg(&g_cols[j]);
        int c1 = __ldg(&g_cols[j + 1]);
        float v0 = dr * g_dinv[c0];
        float v1 = dr * g_dinv[c1];
        const float4* p0 = (const float4*)((c0 < split)
                              ? xu + (size_t)c0 * D
                              : xi + (size_t)(c0 - split) * D);
        const float4* p1 = (const float4*)((c1 < split)
                              ? xu + (size_t)c1 * D
                              : xi + (size_t)(c1 - split) * D);
        float4 r0 = p0[lane];
        float4 r1 = p1[lane];
        a.x = fmaf(v0, r0.x, fmaf(v1, r1.x, a.x));
        a.y = fmaf(v0, r0.y, fmaf(v1, r1.y, a.y));
        a.z = fmaf(v0, r0.z, fmaf(v1, r1.z, a.z));
        a.w = fmaf(v0, r0.w, fmaf(v1, r1.w, a.w));
    }
    if (j < end) {
        int c = __ldg(&g_cols[j]);
        float v = dr * g_dinv[c];
        const float4* p = (const float4*)((c < split)
                              ? xu + (size_t)c * D
                              : xi + (size_t)(c - split) * D);
        float4 r = p[lane];
        a.x = fmaf(v, r.x, a.x);
        a.y = fmaf(v, r.y, a.y);
        a.z = fmaf(v, r.z, a.z);
        a.w = fmaf(v, r.w, a.w);
    }

    float4* ao = (float4*)(acc + (size_t)row * D);
    if (layer == 0) {
        const float* er = (row < split) ? xu + (size_t)row * D
                                        : xi + (size_t)(row - split) * D;
        float4 e = ((const float4*)er)[lane];
        ((float4*)(xout + (size_t)row * D))[lane] = a;
        ao[lane] = make_float4(e.x + a.x, e.y + a.y, e.z + a.z, e.w + a.w);
    } else if (layer == 1) {
        ((float4*)(xout + (size_t)row * D))[lane] = a;
        float4 s = ao[lane];
        ao[lane] = make_float4(s.x + a.x, s.y + a.y, s.z + a.z, s.w + a.w);
    } else {
        float4 s = ao[lane];
        ao[lane] = make_float4((s.x + a.x) * 0.25f, (s.y + a.y) * 0.25f,
                               (s.z + a.z) * 0.25f, (s.w + a.w) * 0.25f);
    }
}

// --------------------------------------------------------------- launch ----

extern "C" void kernel_launch(void* const* d_in, const int* in_sizes, int n_in,
                              void* d_out, int out_size) {
    const float* uw = (const float*)d_in[0];
    const float* iw = (const float*)d_in[1];
    const int*   ei = (const int*)d_in[2];

    int num_users = in_sizes[0] / D;
    int num_items = in_sizes[1] / D;
    int n_nodes = num_users + num_items;
    int nE = in_sizes[2] / 2;          // edge_index is [2, 2E]
    const int* src = ei;
    const int* dst = ei + nE;
    float* out = (float*)d_out;

    // CSR build
    zero_deg_kernel<<<(n_nodes + 255) / 256, 256>>>(n_nodes);
    hist_kernel<<<(nE + 255) / 256, 256>>>(src, nE);
    int nb = (n_nodes + SCAN_BLK - 1) / SCAN_BLK;
    scan1_kernel<<<nb, SCAN_BLK>>>(n_nodes);
    scan2_kernel<<<1, 256>>>(nb);
    scan3_kernel<<<(n_nodes + 255) / 256, 256>>>(n_nodes);
    scatter_kernel<<<(nE + 255) / 256, 256>>>(src, dst, nE);

    // 3 propagation layers (warp per row)
    int blocks = (n_nodes * 32 + 255) / 256;
    spmm_kernel<<<blocks, 256>>>(uw, iw, num_users, n_nodes, out, 0);
    spmm_kernel<<<blocks, 256>>>(uw, iw, num_users, n_nodes, out, 1);
    spmm_kernel<<<blocks, 256>>>(uw, iw, num_users, n_nodes, out, 2);
}

// round 4
// speedup vs baseline: 1.2772x; 1.2772x over previous
#include <cuda_runtime.h>
#include <cuda_fp16.h>

// LightGCN: 3-layer normalized-adjacency propagation, fp16 intermediates.
//   x_{k+1}[s] = dinv[s] * sum_e dinv[dst(e)] * x_k[dst(e)]
//   out = (emb + x1 + x2 + x3) / 4   (emb term kept exact fp32)
//
// NOTE: device globals are ONLY referenced from device code (passing a
// __device__ symbol as a host-side kernel arg gives the host shadow
// address — that was the R2/R3 bug).

#define D 128
#define MAX_NODES 160000
#define MAX_EDGES 2200000
#define SCAN_BLK 1024

struct __align__(8) Half4 {
    __half2 h01;
    __half2 h23;
};

__device__ int   g_deg[MAX_NODES];
__device__ int   g_rowptr[MAX_NODES + 1];
__device__ int   g_cursor[MAX_NODES];
__device__ float g_dinv[MAX_NODES];
__device__ int   g_cols[MAX_EDGES];
__device__ Half4 g_eh [(size_t)MAX_NODES * 32];   // fp16 emb
__device__ Half4 g_x1h[(size_t)MAX_NODES * 32];   // fp16 x1
__device__ Half4 g_x2h[(size_t)MAX_NODES * 32];   // fp16 x2
__device__ int   g_bsum[256];
__device__ int   g_bpre[256];
__device__ int   g_total;

// ---------------------------------------------------------------- setup ----

__global__ void zero_deg_kernel(int n) {
    int i = blockIdx.x * blockDim.x + threadIdx.x;
    if (i < n) g_deg[i] = 0;
}

__global__ void hist_kernel(const int* __restrict__ src, int nE) {
    int e = blockIdx.x * blockDim.x + threadIdx.x;
    if (e < nE) atomicAdd(&g_deg[src[e]], 1);
}

__global__ void scan1_kernel(int n) {
    __shared__ int sh[SCAN_BLK];
    int tid = threadIdx.x;
    int i = blockIdx.x * SCAN_BLK + tid;
    int v = (i < n) ? g_deg[i] : 0;
    sh[tid] = v;
    __syncthreads();
    for (int off = 1; off < SCAN_BLK; off <<= 1) {
        int t = (tid >= off) ? sh[tid - off] : 0;
        __syncthreads();
        sh[tid] += t;
        __syncthreads();
    }
    if (i < n) g_rowptr[i] = sh[tid] - v;
    if (tid == SCAN_BLK - 1) g_bsum[blockIdx.x] = sh[tid];
}

__global__ void scan2_kernel(int nb) {
    __shared__ int sh[256];
    int tid = threadIdx.x;
    int v = (tid < nb) ? g_bsum[tid] : 0;
    sh[tid] = v;
    __syncthreads();
    for (int off = 1; off < 256; off <<= 1) {
        int t = (tid >= off) ? sh[tid - off] : 0;
        __syncthreads();
        sh[tid] += t;
        __syncthreads();
    }
    if (tid < nb) g_bpre[tid] = sh[tid] - v;
    if (tid == 255) g_total = sh[255];
}

__global__ void scan3_kernel(int n) {
    int i = blockIdx.x * blockDim.x + threadIdx.x;
    if (i < n) {
        int rp = g_rowptr[i] + g_bpre[i >> 10];
        g_rowptr[i] = rp;
        g_cursor[i] = rp;
        int d = g_deg[i];
        g_dinv[i] = (d > 0) ? rsqrtf((float)d) : 0.0f;
    }
    if (i == 0) g_rowptr[n] = g_total;
}

__global__ void scatter_kernel(const int* __restrict__ src,
                               const int* __restrict__ dst, int nE) {
    int e = blockIdx.x * blockDim.x + threadIdx.x;
    if (e < nE) {
        int s = src[e];
        int pos = atomicAdd(&g_cursor[s], 1);
        g_cols[pos] = dst[e];
    }
}

// emb fp32 -> fp16 concat. One thread per Half4 (4 dims).
__global__ void convert_kernel(const float* __restrict__ uw,
                               const float* __restrict__ iw,
                               int num_users, int n_nodes) {
    int i = blockIdx.x * blockDim.x + threadIdx.x;
    if (i >= n_nodes * 32) return;
    int node = i >> 5, lane = i & 31;
    const float4* srcp = (const float4*)((node < num_users)
                            ? uw + (size_t)node * D
                            : iw + (size_t)(node - num_users) * D);
    float4 f = srcp[lane];
    Half4 r;
    r.h01 = __floats2half2_rn(f.x, f.y);
    r.h23 = __floats2half2_rn(f.z, f.w);
    g_eh[i] = r;
}

// ----------------------------------------------------------------- SpMM ----
// One warp per row; lane owns dims [4*lane, 4*lane+4) as one Half4.

__device__ __forceinline__ void acc_edge(float v, Half4 r,
                                         float& a0, float& a1, float& a2, float& a3) {
    float2 f01 = __half22float2(r.h01);
    float2 f23 = __half22float2(r.h23);
    a0 = fmaf(v, f01.x, a0);
    a1 = fmaf(v, f01.y, a1);
    a2 = fmaf(v, f23.x, a2);
    a3 = fmaf(v, f23.y, a3);
}

__device__ __forceinline__ void gather_row(const Half4* __restrict__ xin,
                                           int start, int end, int lane,
                                           float& a0, float& a1, float& a2, float& a3) {
    int j = start;
    for (; j + 4 <= end; j += 4) {
        int c0 = __ldg(&g_cols[j]);
        int c1 = __ldg(&g_cols[j + 1]);
        int c2 = __ldg(&g_cols[j + 2]);
        int c3 = __ldg(&g_cols[j + 3]);
        float v0 = g_dinv[c0], v1 = g_dinv[c1], v2 = g_dinv[c2], v3 = g_dinv[c3];
        Half4 r0 = xin[(size_t)c0 * 32 + lane];
        Half4 r1 = xin[(size_t)c1 * 32 + lane];
        Half4 r2 = xin[(size_t)c2 * 32 + lane];
        Half4 r3 = xin[(size_t)c3 * 32 + lane];
        acc_edge(v0, r0, a0, a1, a2, a3);
        acc_edge(v1, r1, a0, a1, a2, a3);
        acc_edge(v2, r2, a0, a1, a2, a3);
        acc_edge(v3, r3, a0, a1, a2, a3);
    }
    for (; j < end; j++) {
        int c = __ldg(&g_cols[j]);
        float v = g_dinv[c];
        Half4 r = xin[(size_t)c * 32 + lane];
        acc_edge(v, r, a0, a1, a2, a3);
    }
}

// layers 1 & 2: gather fp16 -> write fp16.  Buffers chosen IN DEVICE CODE.
__global__ void __launch_bounds__(256)
spmm_mid(int layer, int n_nodes) {
    int warp = (blockIdx.x * blockDim.x + threadIdx.x) >> 5;
    int lane = threadIdx.x & 31;
    if (warp >= n_nodes) return;

    const Half4* xin  = (layer == 1) ? g_eh  : g_x1h;
    Half4*       xout = (layer == 1) ? g_x1h : g_x2h;

    float dr = g_dinv[warp];
    int start = g_rowptr[warp];
    int end   = g_rowptr[warp + 1];

    float a0 = 0.f, a1 = 0.f, a2 = 0.f, a3 = 0.f;
    gather_row(xin, start, end, lane, a0, a1, a2, a3);

    Half4 r;
    r.h01 = __floats2half2_rn(a0 * dr, a1 * dr);
    r.h23 = __floats2half2_rn(a2 * dr, a3 * dr);
    xout[(size_t)warp * 32 + lane] = r;
}

// layer 3: gather x2_h, fuse out = (emb + x1 + x2 + x3)/4
__global__ void __launch_bounds__(256)
spmm_last(const float* __restrict__ uw, const float* __restrict__ iw,
          int num_users, int n_nodes, float* __restrict__ out) {
    int warp = (blockIdx.x * blockDim.x + threadIdx.x) >> 5;
    int lane = threadIdx.x & 31;
    if (warp >= n_nodes) return;

    float dr = g_dinv[warp];
    int start = g_rowptr[warp];
    int end   = g_rowptr[warp + 1];

    float a0 = 0.f, a1 = 0.f, a2 = 0.f, a3 = 0.f;
    gather_row(g_x2h, start, end, lane, a0, a1, a2, a3);
    a0 *= dr; a1 *= dr; a2 *= dr; a3 *= dr;      // x3

    Half4 w1 = g_x1h[(size_t)warp * 32 + lane];
    Half4 w2 = g_x2h[(size_t)warp * 32 + lane];
    float2 p01 = __half22float2(w1.h01);
    float2 p23 = __half22float2(w1.h23);
    float2 q01 = __half22float2(w2.h01);
    float2 q23 = __half22float2(w2.h23);

    const float4* ep = (const float4*)((warp < num_users)
                          ? uw + (size_t)warp * D
                          : iw + (size_t)(warp - num_users) * D);
    float4 e = ep[lane];

    float4 o;
    o.x = (e.x + p01.x + q01.x + a0) * 0.25f;
    o.y = (e.y + p01.y + q01.y + a1) * 0.25f;
    o.z = (e.z + p23.x + q23.x + a2) * 0.25f;
    o.w = (e.w + p23.y + q23.y + a3) * 0.25f;
    ((float4*)(out + (size_t)warp * D))[lane] = o;
}

// --------------------------------------------------------------- launch ----

extern "C" void kernel_launch(void* const* d_in, const int* in_sizes, int n_in,
                              void* d_out, int out_size) {
    const float* uw = (const float*)d_in[0];
    const float* iw = (const float*)d_in[1];
    const int*   ei = (const int*)d_in[2];

    int num_users = in_sizes[0] / D;
    int num_items = in_sizes[1] / D;
    int n_nodes = num_users + num_items;
    int nE = in_sizes[2] / 2;
    const int* src = ei;
    const int* dst = ei + nE;
    float* out = (float*)d_out;

    // CSR build
    zero_deg_kernel<<<(n_nodes + 255) / 256, 256>>>(n_nodes);
    hist_kernel<<<(nE + 255) / 256, 256>>>(src, nE);
    int nb = (n_nodes + SCAN_BLK - 1) / SCAN_BLK;
    scan1_kernel<<<nb, SCAN_BLK>>>(n_nodes);
    scan2_kernel<<<1, 256>>>(nb);
    scan3_kernel<<<(n_nodes + 255) / 256, 256>>>(n_nodes);
    scatter_kernel<<<(nE + 255) / 256, 256>>>(src, dst, nE);

    // fp16 emb
    convert_kernel<<<(n_nodes * 32 + 255) / 256, 256>>>(uw, iw, num_users, n_nodes);

    // 3 propagation layers
    int blocks = (n_nodes * 32 + 255) / 256;
    spmm_mid<<<blocks, 256>>>(1, n_nodes);
    spmm_mid<<<blocks, 256>>>(2, n_nodes);
    spmm_last<<<blocks, 256>>>(uw, iw, num_users, n_nodes, out);
}

// round 5
// speedup vs baseline: 1.3570x; 1.0624x over previous
#include <cuda_runtime.h>
#include <cuda_fp16.h>

// LightGCN: 3-layer normalized-adjacency propagation, fp16 intermediates.
//   x_{k+1}[s] = dinv[s] * sum_e dinv[dst(e)] * x_k[dst(e)]
//   out = (emb + x1 + x2 + x3) / 4   (emb term kept exact fp32)
//
// CSR stores per-edge {col, dinv[col]} records so the SpMM inner loop has no
// dependent dinv gather. Device globals referenced only from device code.

#define D 128
#define MAX_NODES 160000
#define MAX_EDGES 2200000
#define SCAN_BLK 1024

struct __align__(8) Half4 {
    __half2 h01;
    __half2 h23;
};

struct __align__(8) ColV {
    int   c;
    float v;
};

__device__ int   g_deg[MAX_NODES];
__device__ int   g_rowptr[MAX_NODES + 1];
__device__ int   g_cursor[MAX_NODES];
__device__ float g_dinv[MAX_NODES];
__device__ ColV  g_cve[MAX_EDGES];
__device__ Half4 g_eh [(size_t)MAX_NODES * 32];   // fp16 emb
__device__ Half4 g_x1h[(size_t)MAX_NODES * 32];   // fp16 x1
__device__ Half4 g_x2h[(size_t)MAX_NODES * 32];   // fp16 x2
__device__ int   g_bsum[256];

// ---------------------------------------------------------------- setup ----

// zero degrees + convert emb fp32 -> fp16 (merged; independent work)
__global__ void init_kernel(const float* __restrict__ uw,
                            const float* __restrict__ iw,
                            int num_users, int n_nodes) {
    int i = blockIdx.x * blockDim.x + threadIdx.x;
    if (i < n_nodes) g_deg[i] = 0;
    if (i >= n_nodes * 32) return;
    int node = i >> 5, lane = i & 31;
    const float4* srcp = (const float4*)((node < num_users)
                            ? uw + (size_t)node * D
                            : iw + (size_t)(node - num_users) * D);
    float4 f = srcp[lane];
    Half4 r;
    r.h01 = __floats2half2_rn(f.x, f.y);
    r.h23 = __floats2half2_rn(f.z, f.w);
    g_eh[i] = r;
}

__global__ void hist_kernel(const int* __restrict__ src, int nE) {
    int e = blockIdx.x * blockDim.x + threadIdx.x;
    if (e < nE) atomicAdd(&g_deg[src[e]], 1);
}

// per-1024-block exclusive scan of g_deg into g_rowptr; block sums to g_bsum
__global__ void scan1_kernel(int n) {
    __shared__ int sh[SCAN_BLK];
    int tid = threadIdx.x;
    int i = blockIdx.x * SCAN_BLK + tid;
    int v = (i < n) ? g_deg[i] : 0;
    sh[tid] = v;
    __syncthreads();
    for (int off = 1; off < SCAN_BLK; off <<= 1) {
        int t = (tid >= off) ? sh[tid - off] : 0;
        __syncthreads();
        sh[tid] += t;
        __syncthreads();
    }
    if (i < n) g_rowptr[i] = sh[tid] - v;
    if (tid == SCAN_BLK - 1) g_bsum[blockIdx.x] = sh[tid];
}

// merged scan2+scan3: each 256-thread block lies inside one 1024-chunk,
// so it needs a single block-prefix. Redundantly reduce bsum in smem.
__global__ void scan23_kernel(int n, int nb) {
    __shared__ int sh[256];
    int tid = threadIdx.x;
    int i = blockIdx.x * 256 + tid;
    int chunk = (blockIdx.x * 256) >> 10;          // same for whole block

    int b = (tid < nb) ? g_bsum[tid] : 0;

    // prefix = sum_{k<chunk} bsum[k]
    sh[tid] = (tid < chunk) ? b : 0;
    __syncthreads();
    for (int off = 128; off > 0; off >>= 1) {
        if (tid < off) sh[tid] += sh[tid + off];
        __syncthreads();
    }
    int prefix = sh[0];
    __syncthreads();

    // total = sum_{k<nb} bsum[k]
    sh[tid] = b;
    __syncthreads();
    for (int off = 128; off > 0; off >>= 1) {
        if (tid < off) sh[tid] += sh[tid + off];
        __syncthreads();
    }
    int total = sh[0];

    if (i < n) {
        int rp = g_rowptr[i] + prefix;
        g_rowptr[i] = rp;
        g_cursor[i] = rp;
        int d = g_deg[i];
        g_dinv[i] = (d > 0) ? rsqrtf((float)d) : 0.0f;
    }
    if (i == 0) g_rowptr[n] = total;
}

// scatter edges into CSR, storing {dst, dinv[dst]} per slot
__global__ void scatter_kernel(const int* __restrict__ src,
                               const int* __restrict__ dst, int nE) {
    int e = blockIdx.x * blockDim.x + threadIdx.x;
    if (e < nE) {
        int s = src[e];
        int d = dst[e];
        int pos = atomicAdd(&g_cursor[s], 1);
        ColV cv;
        cv.c = d;
        cv.v = g_dinv[d];
        g_cve[pos] = cv;
    }
}

// ----------------------------------------------------------------- SpMM ----
// One warp per row; lane owns dims [4*lane, 4*lane+4) as one Half4.

__device__ __forceinline__ void acc_edge(float v, Half4 r,
                                         float& a0, float& a1, float& a2, float& a3) {
    float2 f01 = __half22float2(r.h01);
    float2 f23 = __half22float2(r.h23);
    a0 = fmaf(v, f01.x, a0);
    a1 = fmaf(v, f01.y, a1);
    a2 = fmaf(v, f23.x, a2);
    a3 = fmaf(v, f23.y, a3);
}

__device__ __forceinline__ void gather_row(const Half4* __restrict__ xin,
                                           int start, int end, int lane,
                                           float& a0, float& a1, float& a2, float& a3) {
    int j = start;
    for (; j + 4 <= end; j += 4) {
        ColV e0 = g_cve[j];
        ColV e1 = g_cve[j + 1];
        ColV e2 = g_cve[j + 2];
        ColV e3 = g_cve[j + 3];
        Half4 r0 = xin[(size_t)e0.c * 32 + lane];
        Half4 r1 = xin[(size_t)e1.c * 32 + lane];
        Half4 r2 = xin[(size_t)e2.c * 32 + lane];
        Half4 r3 = xin[(size_t)e3.c * 32 + lane];
        acc_edge(e0.v, r0, a0, a1, a2, a3);
        acc_edge(e1.v, r1, a0, a1, a2, a3);
        acc_edge(e2.v, r2, a0, a1, a2, a3);
        acc_edge(e3.v, r3, a0, a1, a2, a3);
    }
    for (; j < end; j++) {
        ColV e = g_cve[j];
        Half4 r = xin[(size_t)e.c * 32 + lane];
        acc_edge(e.v, r, a0, a1, a2, a3);
    }
}

// layers 1 & 2: gather fp16 -> write fp16.  Buffers chosen IN DEVICE CODE.
__global__ void __launch_bounds__(256)
spmm_mid(int layer, int n_nodes) {
    int warp = (blockIdx.x * blockDim.x + threadIdx.x) >> 5;
    int lane = threadIdx.x & 31;
    if (warp >= n_nodes) return;

    const Half4* xin  = (layer == 1) ? g_eh  : g_x1h;
    Half4*       xout = (layer == 1) ? g_x1h : g_x2h;

    float dr = g_dinv[warp];
    int start = __ldg(&g_rowptr[warp]);
    int end   = __ldg(&g_rowptr[warp + 1]);

    float a0 = 0.f, a1 = 0.f, a2 = 0.f, a3 = 0.f;
    gather_row(xin, start, end, lane, a0, a1, a2, a3);

    Half4 r;
    r.h01 = __floats2half2_rn(a0 * dr, a1 * dr);
    r.h23 = __floats2half2_rn(a2 * dr, a3 * dr);
    xout[(size_t)warp * 32 + lane] = r;
}

// layer 3: gather x2_h, fuse out = (emb + x1 + x2 + x3)/4
__global__ void __launch_bounds__(256)
spmm_last(const float* __restrict__ uw, const float* __restrict__ iw,
          int num_users, int n_nodes, float* __restrict__ out) {
    int warp = (blockIdx.x * blockDim.x + threadIdx.x) >> 5;
    int lane = threadIdx.x & 31;
    if (warp >= n_nodes) return;

    float dr = g_dinv[warp];
    int start = __ldg(&g_rowptr[warp]);
    int end   = __ldg(&g_rowptr[warp + 1]);

    float a0 = 0.f, a1 = 0.f, a2 = 0.f, a3 = 0.f;
    gather_row(g_x2h, start, end, lane, a0, a1, a2, a3);
    a0 *= dr; a1 *= dr; a2 *= dr; a3 *= dr;      // x3

    Half4 w1 = g_x1h[(size_t)warp * 32 + lane];
    Half4 w2 = g_x2h[(size_t)warp * 32 + lane];
    float2 p01 = __half22float2(w1.h01);
    float2 p23 = __half22float2(w1.h23);
    float2 q01 = __half22float2(w2.h01);
    float2 q23 = __half22float2(w2.h23);

    const float4* ep = (const float4*)((warp < num_users)
                          ? uw + (size_t)warp * D
                          : iw + (size_t)(warp - num_users) * D);
    float4 e = ep[lane];

    float4 o;
    o.x = (e.x + p01.x + q01.x + a0) * 0.25f;
    o.y = (e.y + p01.y + q01.y + a1) * 0.25f;
    o.z = (e.z + p23.x + q23.x + a2) * 0.25f;
    o.w = (e.w + p23.y + q23.y + a3) * 0.25f;
    ((float4*)(out + (size_t)warp * D))[lane] = o;
}

// --------------------------------------------------------------- launch ----

extern "C" void kernel_launch(void* const* d_in, const int* in_sizes, int n_in,
                              void* d_out, int out_size) {
    const float* uw = (const float*)d_in[0];
    const float* iw = (const float*)d_in[1];
    const int*   ei = (const int*)d_in[2];

    int num_users = in_sizes[0] / D;
    int num_items = in_sizes[1] / D;
    int n_nodes = num_users + num_items;
    int nE = in_sizes[2] / 2;
    const int* src = ei;
    const int* dst = ei + nE;
    float* out = (float*)d_out;

    // setup + CSR build
    init_kernel<<<(n_nodes * 32 + 255) / 256, 256>>>(uw, iw, num_users, n_nodes);
    hist_kernel<<<(nE + 255) / 256, 256>>>(src, nE);
    int nb = (n_nodes + SCAN_BLK - 1) / SCAN_BLK;
    scan1_kernel<<<nb, SCAN_BLK>>>(n_nodes);
    scan23_kernel<<<(n_nodes + 255) / 256, 256>>>(n_nodes, nb);
    scatter_kernel<<<(nE + 255) / 256, 256>>>(src, dst, nE);

    // 3 propagation layers
    int blocks = (n_nodes * 32 + 255) / 256;
    spmm_mid<<<blocks, 256>>>(1, n_nodes);
    spmm_mid<<<blocks, 256>>>(2, n_nodes);
    spmm_last<<<blocks, 256>>>(uw, iw, num_users, n_nodes, out);
}

// round 6
// speedup vs baseline: 1.3609x; 1.0029x over previous
#include <cuda_runtime.h>
#include <cuda_fp16.h>

// LightGCN: 3-layer normalized-adjacency propagation, fp16 intermediates.
//   x_{k+1}[s] = dinv[s] * sum_e dinv[dst(e)] * x_k[dst(e)]
//   out = (emb + x1 + x2 + x3) / 4   (emb term kept exact fp32)
//
// CSR stores per-edge {col, dinv[col]} records so the SpMM inner loop has no
// dependent dinv gather. Device globals referenced only from device code.

#define D 128
#define MAX_NODES 160000
#define MAX_EDGES 2200000
#define SCAN_BLK 1024

struct __align__(8) Half4 {
    __half2 h01;
    __half2 h23;
};

struct __align__(8) ColV {
    int   c;
    float v;
};

__device__ int   g_deg[MAX_NODES];
__device__ int   g_rowptr[MAX_NODES + 1];
__device__ int   g_cursor[MAX_NODES];
__device__ float g_dinv[MAX_NODES];
__device__ ColV  g_cve[MAX_EDGES];
__device__ Half4 g_eh [(size_t)MAX_NODES * 32];   // fp16 emb
__device__ Half4 g_x1h[(size_t)MAX_NODES * 32];   // fp16 x1
__device__ Half4 g_x2h[(size_t)MAX_NODES * 32];   // fp16 x2
__device__ int   g_bsum[256];

// ---------------------------------------------------------------- setup ----

__global__ void zero_deg_kernel(int n) {
    int i = blockIdx.x * blockDim.x + threadIdx.x;
    if (i < n) g_deg[i] = 0;
}

// merged: degree histogram (first nE threads) + emb fp32->fp16 convert (all)
__global__ void histconv_kernel(const float* __restrict__ uw,
                                const float* __restrict__ iw,
                                const int* __restrict__ src,
                                int nE, int num_users, int n_nodes) {
    int i = blockIdx.x * blockDim.x + threadIdx.x;
    if (i < nE) atomicAdd(&g_deg[src[i]], 1);
    if (i >= n_nodes * 32) return;
    int node = i >> 5, lane = i & 31;
    const float4* srcp = (const float4*)((node < num_users)
                            ? uw + (size_t)node * D
                            : iw + (size_t)(node - num_users) * D);
    float4 f = srcp[lane];
    Half4 r;
    r.h01 = __floats2half2_rn(f.x, f.y);
    r.h23 = __floats2half2_rn(f.z, f.w);
    g_eh[i] = r;
}

// per-1024-block exclusive scan of g_deg into g_rowptr; block sums to g_bsum
__global__ void scan1_kernel(int n) {
    __shared__ int sh[SCAN_BLK];
    int tid = threadIdx.x;
    int i = blockIdx.x * SCAN_BLK + tid;
    int v = (i < n) ? g_deg[i] : 0;
    sh[tid] = v;
    __syncthreads();
    for (int off = 1; off < SCAN_BLK; off <<= 1) {
        int t = (tid >= off) ? sh[tid - off] : 0;
        __syncthreads();
        sh[tid] += t;
        __syncthreads();
    }
    if (i < n) g_rowptr[i] = sh[tid] - v;
    if (tid == SCAN_BLK - 1) g_bsum[blockIdx.x] = sh[tid];
}

// merged scan2+scan3: each 256-thread block lies inside one 1024-chunk,
// so it needs a single block-prefix. Redundantly reduce bsum in smem.
__global__ void scan23_kernel(int n, int nb) {
    __shared__ int sh[256];
    int tid = threadIdx.x;
    int i = blockIdx.x * 256 + tid;
    int chunk = (blockIdx.x * 256) >> 10;          // same for whole block

    int b = (tid < nb) ? g_bsum[tid] : 0;

    // prefix = sum_{k<chunk} bsum[k]
    sh[tid] = (tid < chunk) ? b : 0;
    __syncthreads();
    for (int off = 128; off > 0; off >>= 1) {
        if (tid < off) sh[tid] += sh[tid + off];
        __syncthreads();
    }
    int prefix = sh[0];
    __syncthreads();

    // total = sum_{k<nb} bsum[k]
    sh[tid] = b;
    __syncthreads();
    for (int off = 128; off > 0; off >>= 1) {
        if (tid < off) sh[tid] += sh[tid + off];
        __syncthreads();
    }
    int total = sh[0];

    if (i < n) {
        int rp = g_rowptr[i] + prefix;
        g_rowptr[i] = rp;
        g_cursor[i] = rp;
        int d = g_deg[i];
        g_dinv[i] = (d > 0) ? rsqrtf((float)d) : 0.0f;
    }
    if (i == 0) g_rowptr[n] = total;
}

// scatter edges into CSR, storing {dst, dinv[dst]} per slot. 2 edges/thread.
__global__ void scatter_kernel(const int* __restrict__ src,
                               const int* __restrict__ dst, int nE) {
    int t = blockIdx.x * blockDim.x + threadIdx.x;
    int e = t * 2;
    if (e + 1 < nE) {
        int2 s2 = *(const int2*)(src + e);
        int2 d2 = *(const int2*)(dst + e);
        int p0 = atomicAdd(&g_cursor[s2.x], 1);
        int p1 = atomicAdd(&g_cursor[s2.y], 1);
        ColV cv0; cv0.c = d2.x; cv0.v = g_dinv[d2.x];
        ColV cv1; cv1.c = d2.y; cv1.v = g_dinv[d2.y];
        g_cve[p0] = cv0;
        g_cve[p1] = cv1;
    } else if (e < nE) {
        int s = src[e];
        int d = dst[e];
        int pos = atomicAdd(&g_cursor[s], 1);
        ColV cv; cv.c = d; cv.v = g_dinv[d];
        g_cve[pos] = cv;
    }
}

// ----------------------------------------------------------------- SpMM ----
// One warp per row; lane owns dims [4*lane, 4*lane+4) as one Half4.

__device__ __forceinline__ void acc_edge(float v, Half4 r,
                                         float& a0, float& a1, float& a2, float& a3) {
    float2 f01 = __half22float2(r.h01);
    float2 f23 = __half22float2(r.h23);
    a0 = fmaf(v, f01.x, a0);
    a1 = fmaf(v, f01.y, a1);
    a2 = fmaf(v, f23.x, a2);
    a3 = fmaf(v, f23.y, a3);
}

__device__ __forceinline__ void gather_row(const Half4* __restrict__ xin,
                                           int start, int end, int lane,
                                           float& a0, float& a1, float& a2, float& a3) {
    int j = start;
    for (; j + 4 <= end; j += 4) {
        ColV e0 = g_cve[j];
        ColV e1 = g_cve[j + 1];
        ColV e2 = g_cve[j + 2];
        ColV e3 = g_cve[j + 3];
        Half4 r0 = xin[(size_t)e0.c * 32 + lane];
        Half4 r1 = xin[(size_t)e1.c * 32 + lane];
        Half4 r2 = xin[(size_t)e2.c * 32 + lane];
        Half4 r3 = xin[(size_t)e3.c * 32 + lane];
        acc_edge(e0.v, r0, a0, a1, a2, a3);
        acc_edge(e1.v, r1, a0, a1, a2, a3);
        acc_edge(e2.v, r2, a0, a1, a2, a3);
        acc_edge(e3.v, r3, a0, a1, a2, a3);
    }
    for (; j < end; j++) {
        ColV e = g_cve[j];
        Half4 r = xin[(size_t)e.c * 32 + lane];
        acc_edge(e.v, r, a0, a1, a2, a3);
    }
}

// layers 1 & 2: gather fp16 -> write fp16.  Buffers chosen IN DEVICE CODE.
__global__ void __launch_bounds__(256)
spmm_mid(int layer, int n_nodes) {
    int warp = (blockIdx.x * blockDim.x + threadIdx.x) >> 5;
    int lane = threadIdx.x & 31;
    if (warp >= n_nodes) return;

    const Half4* xin  = (layer == 1) ? g_eh  : g_x1h;
    Half4*       xout = (layer == 1) ? g_x1h : g_x2h;

    float dr = g_dinv[warp];
    int start = __ldg(&g_rowptr[warp]);
    int end   = __ldg(&g_rowptr[warp + 1]);

    float a0 = 0.f, a1 = 0.f, a2 = 0.f, a3 = 0.f;
    gather_row(xin, start, end, lane, a0, a1, a2, a3);

    Half4 r;
    r.h01 = __floats2half2_rn(a0 * dr, a1 * dr);
    r.h23 = __floats2half2_rn(a2 * dr, a3 * dr);
    xout[(size_t)warp * 32 + lane] = r;
}

// layer 3: gather x2_h, fuse out = (emb + x1 + x2 + x3)/4
__global__ void __launch_bounds__(256)
spmm_last(const float* __restrict__ uw, const float* __restrict__ iw,
          int num_users, int n_nodes, float* __restrict__ out) {
    int warp = (blockIdx.x * blockDim.x + threadIdx.x) >> 5;
    int lane = threadIdx.x & 31;
    if (warp >= n_nodes) return;

    float dr = g_dinv[warp];
    int start = __ldg(&g_rowptr[warp]);
    int end   = __ldg(&g_rowptr[warp + 1]);

    float a0 = 0.f, a1 = 0.f, a2 = 0.f, a3 = 0.f;
    gather_row(g_x2h, start, end, lane, a0, a1, a2, a3);
    a0 *= dr; a1 *= dr; a2 *= dr; a3 *= dr;      // x3

    Half4 w1 = g_x1h[(size_t)warp * 32 + lane];
    Half4 w2 = g_x2h[(size_t)warp * 32 + lane];
    float2 p01 = __half22float2(w1.h01);
    float2 p23 = __half22float2(w1.h23);
    float2 q01 = __half22float2(w2.h01);
    float2 q23 = __half22float2(w2.h23);

    const float4* ep = (const float4*)((warp < num_users)
                          ? uw + (size_t)warp * D
                          : iw + (size_t)(warp - num_users) * D);
    float4 e = ep[lane];

    float4 o;
    o.x = (e.x + p01.x + q01.x + a0) * 0.25f;
    o.y = (e.y + p01.y + q01.y + a1) * 0.25f;
    o.z = (e.z + p23.x + q23.x + a2) * 0.25f;
    o.w = (e.w + p23.y + q23.y + a3) * 0.25f;
    ((float4*)(out + (size_t)warp * D))[lane] = o;
}

// --------------------------------------------------------------- launch ----

extern "C" void kernel_launch(void* const* d_in, const int* in_sizes, int n_in,
                              void* d_out, int out_size) {
    const float* uw = (const float*)d_in[0];
    const float* iw = (const float*)d_in[1];
    const int*   ei = (const int*)d_in[2];

    int num_users = in_sizes[0] / D;
    int num_items = in_sizes[1] / D;
    int n_nodes = num_users + num_items;
    int nE = in_sizes[2] / 2;
    const int* src = ei;
    const int* dst = ei + nE;
    float* out = (float*)d_out;

    // setup + CSR build
    zero_deg_kernel<<<(n_nodes + 255) / 256, 256>>>(n_nodes);
    histconv_kernel<<<(n_nodes * 32 + 255) / 256, 256>>>(uw, iw, src, nE,
                                                         num_users, n_nodes);
    int nb = (n_nodes + SCAN_BLK - 1) / SCAN_BLK;
    scan1_kernel<<<nb, SCAN_BLK>>>(n_nodes);
    scan23_kernel<<<(n_nodes + 255) / 256, 256>>>(n_nodes, nb);
    scatter_kernel<<<((nE + 1) / 2 + 255) / 256, 256>>>(src, dst, nE);

    // 3 propagation layers
    int blocks = (n_nodes * 32 + 255) / 256;
    spmm_mid<<<blocks, 256>>>(1, n_nodes);
    spmm_mid<<<blocks, 256>>>(2, n_nodes);
    spmm_last<<<blocks, 256>>>(uw, iw, num_users, n_nodes, out);
}

// round 7
// speedup vs baseline: 1.4140x; 1.0390x over previous
#include <cuda_runtime.h>
#include <cuda_fp16.h>

// LightGCN, y-space formulation with fp16 intermediates.
//   y_k = dinv ⊙ x_k  (y0 = dinv ⊙ emb)
//   S[s]     = sum_{e: src=s} y_k[dst(e)]
//   x_{k+1}  = dinv ⊙ S          y_{k+1} = dinv^2 ⊙ S
//   out = (emb + x1 + x2 + x3)/4, emb term exact fp32,
//         x1 = sqrt(deg) * y1, x2 = sqrt(deg) * y2.
// CSR stores bare 4-byte column ids (no per-edge value needed).

#define D 128
#define MAX_NODES 160000
#define MAX_EDGES 2200000
#define SCAN_BLK 1024

struct __align__(8) Half4 {
    __half2 h01;
    __half2 h23;
};

__device__ int   g_deg[MAX_NODES];          // zeroed at module load; self-zeroed per call
__device__ int   g_rowptr[MAX_NODES + 1];
__device__ int   g_cursor[MAX_NODES];
__device__ float g_dinv[MAX_NODES];
__device__ float g_rinv[MAX_NODES];         // sqrt(deg) (0 if deg==0)
__device__ int   g_cols[MAX_EDGES];
__device__ Half4 g_y0[(size_t)MAX_NODES * 32];
__device__ Half4 g_y1[(size_t)MAX_NODES * 32];
__device__ Half4 g_y2[(size_t)MAX_NODES * 32];
__device__ int   g_bsum[256];

// ---------------------------------------------------------------- setup ----

// degree histogram, 4 edges per thread (int4)
__global__ void hist_kernel(const int* __restrict__ src, int nE) {
    int t = blockIdx.x * blockDim.x + threadIdx.x;
    int e = t * 4;
    if (e + 3 < nE) {
        int4 s4 = *(const int4*)(src + e);
        atomicAdd(&g_deg[s4.x], 1);
        atomicAdd(&g_deg[s4.y], 1);
        atomicAdd(&g_deg[s4.z], 1);
        atomicAdd(&g_deg[s4.w], 1);
    } else {
        for (int k = e; k < nE; k++) atomicAdd(&g_deg[src[k]], 1);
    }
}

// per-1024-block exclusive scan of g_deg into g_rowptr; block sums to g_bsum
__global__ void scan1_kernel(int n) {
    __shared__ int sh[SCAN_BLK];
    int tid = threadIdx.x;
    int i = blockIdx.x * SCAN_BLK + tid;
    int v = (i < n) ? g_deg[i] : 0;
    sh[tid] = v;
    __syncthreads();
    for (int off = 1; off < SCAN_BLK; off <<= 1) {
        int t = (tid >= off) ? sh[tid - off] : 0;
        __syncthreads();
        sh[tid] += t;
        __syncthreads();
    }
    if (i < n) g_rowptr[i] = sh[tid] - v;
    if (tid == SCAN_BLK - 1) g_bsum[blockIdx.x] = sh[tid];
}

// merged scan2+scan3: block-prefix + dinv/rinv + cursor init; self-zero g_deg
__global__ void scan23_kernel(int n, int nb) {
    __shared__ int sh[256];
    int tid = threadIdx.x;
    int i = blockIdx.x * 256 + tid;
    int chunk = (blockIdx.x * 256) >> 10;          // same for whole block

    int b = (tid < nb) ? g_bsum[tid] : 0;

    sh[tid] = (tid < chunk) ? b : 0;
    __syncthreads();
    for (int off = 128; off > 0; off >>= 1) {
        if (tid < off) sh[tid] += sh[tid + off];
        __syncthreads();
    }
    int prefix = sh[0];
    __syncthreads();

    sh[tid] = b;
    __syncthreads();
    for (int off = 128; off > 0; off >>= 1) {
        if (tid < off) sh[tid] += sh[tid + off];
        __syncthreads();
    }
    int total = sh[0];

    if (i < n) {
        int rp = g_rowptr[i] + prefix;
        g_rowptr[i] = rp;
        g_cursor[i] = rp;
        int d = g_deg[i];
        float fd = (float)d;
        g_dinv[i] = (d > 0) ? rsqrtf(fd) : 0.0f;
        g_rinv[i] = (d > 0) ? sqrtf(fd) : 0.0f;
        g_deg[i] = 0;                                // ready for next replay
    }
    if (i == 0) g_rowptr[n] = total;
}

// merged scatter (first (nE+1)/2 threads, 2 edges each) + y0 convert (all)
__global__ void scatcvt_kernel(const float* __restrict__ uw,
                               const float* __restrict__ iw,
                               const int* __restrict__ src,
                               const int* __restrict__ dst,
                               int nE, int num_users, int n_nodes) {
    int i = blockIdx.x * blockDim.x + threadIdx.x;

    int e = i * 2;
    if (e + 1 < nE) {
        int2 s2 = *(const int2*)(src + e);
        int2 d2 = *(const int2*)(dst + e);
        int p0 = atomicAdd(&g_cursor[s2.x], 1);
        int p1 = atomicAdd(&g_cursor[s2.y], 1);
        g_cols[p0] = d2.x;
        g_cols[p1] = d2.y;
    } else if (e < nE) {
        int pos = atomicAdd(&g_cursor[src[e]], 1);
        g_cols[pos] = dst[e];
    }

    if (i >= n_nodes * 32) return;
    int node = i >> 5, lane = i & 31;
    const float4* srcp = (const float4*)((node < num_users)
                            ? uw + (size_t)node * D
                            : iw + (size_t)(node - num_users) * D);
    float4 f = srcp[lane];
    float dv = g_dinv[node];
    Half4 r;
    r.h01 = __floats2half2_rn(f.x * dv, f.y * dv);
    r.h23 = __floats2half2_rn(f.z * dv, f.w * dv);
    g_y0[i] = r;
}

// ----------------------------------------------------------------- SpMM ----
// One warp per row; lane owns dims [4*lane, 4*lane+4) as one Half4.
// Pure sum over neighbors (no per-edge scale).

__device__ __forceinline__ void acc_edge(Half4 r,
                                         float& a0, float& a1, float& a2, float& a3) {
    float2 f01 = __half22float2(r.h01);
    float2 f23 = __half22float2(r.h23);
    a0 += f01.x;
    a1 += f01.y;
    a2 += f23.x;
    a3 += f23.y;
}

__device__ __forceinline__ void gather_row(const Half4* __restrict__ xin,
                                           int start, int end, int lane,
                                           float& a0, float& a1, float& a2, float& a3) {
    int j = start;
    for (; j + 4 <= end; j += 4) {
        int c0 = __ldg(&g_cols[j]);
        int c1 = __ldg(&g_cols[j + 1]);
        int c2 = __ldg(&g_cols[j + 2]);
        int c3 = __ldg(&g_cols[j + 3]);
        Half4 r0 = xin[(size_t)c0 * 32 + lane];
        Half4 r1 = xin[(size_t)c1 * 32 + lane];
        Half4 r2 = xin[(size_t)c2 * 32 + lane];
        Half4 r3 = xin[(size_t)c3 * 32 + lane];
        acc_edge(r0, a0, a1, a2, a3);
        acc_edge(r1, a0, a1, a2, a3);
        acc_edge(r2, a0, a1, a2, a3);
        acc_edge(r3, a0, a1, a2, a3);
    }
    for (; j < end; j++) {
        int c = __ldg(&g_cols[j]);
        Half4 r = xin[(size_t)c * 32 + lane];
        acc_edge(r, a0, a1, a2, a3);
    }
}

// layers 1 & 2: gather y_{k-1} -> write y_k = dinv^2 * sum
__global__ void __launch_bounds__(256)
spmm_mid(int layer, int n_nodes) {
    int warp = (blockIdx.x * blockDim.x + threadIdx.x) >> 5;
    int lane = threadIdx.x & 31;
    if (warp >= n_nodes) return;

    const Half4* xin  = (layer == 1) ? g_y0 : g_y1;
    Half4*       xout = (layer == 1) ? g_y1 : g_y2;

    float dv = g_dinv[warp];
    float w2 = dv * dv;
    int start = __ldg(&g_rowptr[warp]);
    int end   = __ldg(&g_rowptr[warp + 1]);

    float a0 = 0.f, a1 = 0.f, a2 = 0.f, a3 = 0.f;
    gather_row(xin, start, end, lane, a0, a1, a2, a3);

    Half4 r;
    r.h01 = __floats2half2_rn(a0 * w2, a1 * w2);
    r.h23 = __floats2half2_rn(a2 * w2, a3 * w2);
    xout[(size_t)warp * 32 + lane] = r;
}

// layer 3: gather y2 -> x3 = dinv*sum; fuse out = (emb + x1 + x2 + x3)/4
// with x1 = rinv*y1, x2 = rinv*y2.
__global__ void __launch_bounds__(256)
spmm_last(const float* __restrict__ uw, const float* __restrict__ iw,
          int num_users, int n_nodes, float* __restrict__ out) {
    int warp = (blockIdx.x * blockDim.x + threadIdx.x) >> 5;
    int lane = threadIdx.x & 31;
    if (warp >= n_nodes) return;

    float dv = g_dinv[warp];
    float rv = g_rinv[warp];
    int start = __ldg(&g_rowptr[warp]);
    int end   = __ldg(&g_rowptr[warp + 1]);

    float a0 = 0.f, a1 = 0.f, a2 = 0.f, a3 = 0.f;
    gather_row(g_y2, start, end, lane, a0, a1, a2, a3);
    a0 *= dv; a1 *= dv; a2 *= dv; a3 *= dv;      // x3

    Half4 w1 = g_y1[(size_t)warp * 32 + lane];
    Half4 w2 = g_y2[(size_t)warp * 32 + lane];
    float2 p01 = __half22float2(w1.h01);
    float2 p23 = __half22float2(w1.h23);
    float2 q01 = __half22float2(w2.h01);
    float2 q23 = __half22float2(w2.h23);

    const float4* ep = (const float4*)((warp < num_users)
                          ? uw + (size_t)warp * D
                          : iw + (size_t)(warp - num_users) * D);
    float4 e = ep[lane];

    float4 o;
    o.x = (e.x + rv * (p01.x + q01.x) + a0) * 0.25f;
    o.y = (e.y + rv * (p01.y + q01.y) + a1) * 0.25f;
    o.z = (e.z + rv * (p23.x + q23.x) + a2) * 0.25f;
    o.w = (e.w + rv * (p23.y + q23.y) + a3) * 0.25f;
    ((float4*)(out + (size_t)warp * D))[lane] = o;
}

// --------------------------------------------------------------- launch ----

extern "C" void kernel_launch(void* const* d_in, const int* in_sizes, int n_in,
                              void* d_out, int out_size) {
    const float* uw = (const float*)d_in[0];
    const float* iw = (const float*)d_in[1];
    const int*   ei = (const int*)d_in[2];

    int num_users = in_sizes[0] / D;
    int num_items = in_sizes[1] / D;
    int n_nodes = num_users + num_items;
    int nE = in_sizes[2] / 2;
    const int* src = ei;
    const int* dst = ei + nE;
    float* out = (float*)d_out;

    // CSR build (g_deg arrives zeroed: module init / self-zero in scan23)
    hist_kernel<<<((nE + 3) / 4 + 255) / 256, 256>>>(src, nE);
    int nb = (n_nodes + SCAN_BLK - 1) / SCAN_BLK;
    scan1_kernel<<<nb, SCAN_BLK>>>(n_nodes);
    scan23_kernel<<<(n_nodes + 255) / 256, 256>>>(n_nodes, nb);
    scatcvt_kernel<<<(n_nodes * 32 + 255) / 256, 256>>>(uw, iw, src, dst, nE,
                                                        num_users, n_nodes);

    // 3 propagation layers
    int blocks = (n_nodes * 32 + 255) / 256;
    spmm_mid<<<blocks, 256>>>(1, n_nodes);
    spmm_mid<<<blocks, 256>>>(2, n_nodes);
    spmm_last<<<blocks, 256>>>(uw, iw, num_users, n_nodes, out);
}

// round 8
// speedup vs baseline: 1.4286x; 1.0103x over previous
#include <cuda_runtime.h>
#include <cuda_fp16.h>

// LightGCN, y-space formulation with fp16 intermediates.
//   y_k = dinv ⊙ x_k  (y0 = dinv ⊙ emb)
//   S[s]     = sum_{e: src=s} y_k[dst(e)]
//   x_{k+1}  = dinv ⊙ S          y_{k+1} = dinv^2 ⊙ S
//   out = (emb + x1 + x2 + x3)/4, emb term exact fp32,
//         x1 = sqrt(deg) * y1, x2 = sqrt(deg) * y2.
// CSR stores bare 4-byte column ids (no per-edge value needed).

#define D 128
#define MAX_NODES 160000
#define MAX_EDGES 2200000
#define SCAN_BLK 1024

struct __align__(8) Half4 {
    __half2 h01;
    __half2 h23;
};

__device__ int   g_deg[MAX_NODES];          // zeroed at load; self-zeroed per call
__device__ int   g_rowptr[MAX_NODES + 1];
__device__ int   g_cursor[MAX_NODES];
__device__ float g_dinv[MAX_NODES];
__device__ float g_rinv[MAX_NODES];         // sqrt(deg) (0 if deg==0)
__device__ int   g_cols[MAX_EDGES];
__device__ Half4 g_y0[(size_t)MAX_NODES * 32];
__device__ Half4 g_y1[(size_t)MAX_NODES * 32];
__device__ Half4 g_y2[(size_t)MAX_NODES * 32];
__device__ int   g_bsum[256];

// ---------------------------------------------------------------- setup ----

// degree histogram, 4 edges per thread (int4)
__global__ void hist_kernel(const int* __restrict__ src, int nE) {
    int t = blockIdx.x * blockDim.x + threadIdx.x;
    int e = t * 4;
    if (e + 3 < nE) {
        int4 s4 = __ldg((const int4*)(src + e));
        atomicAdd(&g_deg[s4.x], 1);
        atomicAdd(&g_deg[s4.y], 1);
        atomicAdd(&g_deg[s4.z], 1);
        atomicAdd(&g_deg[s4.w], 1);
    } else {
        for (int k = e; k < nE; k++) atomicAdd(&g_deg[src[k]], 1);
    }
}

// per-1024-block exclusive scan of g_deg into g_rowptr; block sums to g_bsum
__global__ void scan1_kernel(int n) {
    __shared__ int sh[SCAN_BLK];
    int tid = threadIdx.x;
    int i = blockIdx.x * SCAN_BLK + tid;
    int v = (i < n) ? g_deg[i] : 0;
    sh[tid] = v;
    __syncthreads();
    for (int off = 1; off < SCAN_BLK; off <<= 1) {
        int t = (tid >= off) ? sh[tid - off] : 0;
        __syncthreads();
        sh[tid] += t;
        __syncthreads();
    }
    if (i < n) g_rowptr[i] = sh[tid] - v;
    if (tid == SCAN_BLK - 1) g_bsum[blockIdx.x] = sh[tid];
}

// merged scan2+scan3: block-prefix + dinv/rinv + cursor init; self-zero g_deg
__global__ void scan23_kernel(int n, int nb) {
    __shared__ int sh[256];
    int tid = threadIdx.x;
    int i = blockIdx.x * 256 + tid;
    int chunk = (blockIdx.x * 256) >> 10;          // same for whole block

    int b = (tid < nb) ? g_bsum[tid] : 0;

    sh[tid] = (tid < chunk) ? b : 0;
    __syncthreads();
    for (int off = 128; off > 0; off >>= 1) {
        if (tid < off) sh[tid] += sh[tid + off];
        __syncthreads();
    }
    int prefix = sh[0];
    __syncthreads();

    sh[tid] = b;
    __syncthreads();
    for (int off = 128; off > 0; off >>= 1) {
        if (tid < off) sh[tid] += sh[tid + off];
        __syncthreads();
    }
    int total = sh[0];

    if (i < n) {
        int rp = g_rowptr[i] + prefix;
        g_rowptr[i] = rp;
        g_cursor[i] = rp;
        int d = g_deg[i];
        float fd = (float)d;
        g_dinv[i] = (d > 0) ? rsqrtf(fd) : 0.0f;
        g_rinv[i] = (d > 0) ? sqrtf(fd) : 0.0f;
        g_deg[i] = 0;                                // ready for next replay
    }
    if (i == 0) g_rowptr[n] = total;
}

// scatter + y0 convert with DISJOINT thread ranges:
//   threads [0, nscat)            : 4 edges each (int4), independent atomics
//   threads [nscat, nscat+nconv)  : one Half4 convert each
// scatter range is first so its long-latency blocks launch earliest.
__global__ void scatcvt_kernel(const float* __restrict__ uw,
                               const float* __restrict__ iw,
                               const int* __restrict__ src,
                               const int* __restrict__ dst,
                               int nE, int nscat, int num_users, int n_nodes) {
    int i = blockIdx.x * blockDim.x + threadIdx.x;

    if (i < nscat) {
        int e = i * 4;
        if (e + 3 < nE) {
            int4 s4 = __ldg((const int4*)(src + e));
            int4 d4 = __ldg((const int4*)(dst + e));
            int p0 = atomicAdd(&g_cursor[s4.x], 1);
            int p1 = atomicAdd(&g_cursor[s4.y], 1);
            int p2 = atomicAdd(&g_cursor[s4.z], 1);
            int p3 = atomicAdd(&g_cursor[s4.w], 1);
            g_cols[p0] = d4.x;
            g_cols[p1] = d4.y;
            g_cols[p2] = d4.z;
            g_cols[p3] = d4.w;
        } else {
            for (int k = e; k < nE; k++) {
                int pos = atomicAdd(&g_cursor[src[k]], 1);
                g_cols[pos] = dst[k];
            }
        }
        return;
    }

    int j = i - nscat;
    if (j >= n_nodes * 32) return;
    int node = j >> 5, lane = j & 31;
    const float4* srcp = (const float4*)((node < num_users)
                            ? uw + (size_t)node * D
                            : iw + (size_t)(node - num_users) * D);
    float4 f = srcp[lane];
    float dv = g_dinv[node];
    Half4 r;
    r.h01 = __floats2half2_rn(f.x * dv, f.y * dv);
    r.h23 = __floats2half2_rn(f.z * dv, f.w * dv);
    g_y0[j] = r;
}

// ----------------------------------------------------------------- SpMM ----
// One warp per row; lane owns dims [4*lane, 4*lane+4) as one Half4.
// Pure sum over neighbors (no per-edge scale).

__device__ __forceinline__ void acc_edge(Half4 r,
                                         float& a0, float& a1, float& a2, float& a3) {
    float2 f01 = __half22float2(r.h01);
    float2 f23 = __half22float2(r.h23);
    a0 += f01.x;
    a1 += f01.y;
    a2 += f23.x;
    a3 += f23.y;
}

__device__ __forceinline__ void gather_row(const Half4* __restrict__ xin,
                                           int start, int end, int lane,
                                           float& a0, float& a1, float& a2, float& a3) {
    int j = start;
    for (; j + 4 <= end; j += 4) {
        int c0 = __ldg(&g_cols[j]);
        int c1 = __ldg(&g_cols[j + 1]);
        int c2 = __ldg(&g_cols[j + 2]);
        int c3 = __ldg(&g_cols[j + 3]);
        Half4 r0 = xin[(size_t)c0 * 32 + lane];
        Half4 r1 = xin[(size_t)c1 * 32 + lane];
        Half4 r2 = xin[(size_t)c2 * 32 + lane];
        Half4 r3 = xin[(size_t)c3 * 32 + lane];
        acc_edge(r0, a0, a1, a2, a3);
        acc_edge(r1, a0, a1, a2, a3);
        acc_edge(r2, a0, a1, a2, a3);
        acc_edge(r3, a0, a1, a2, a3);
    }
    for (; j < end; j++) {
        int c = __ldg(&g_cols[j]);
        Half4 r = xin[(size_t)c * 32 + lane];
        acc_edge(r, a0, a1, a2, a3);
    }
}

// layers 1 & 2: gather y_{k-1} -> write y_k = dinv^2 * sum
__global__ void __launch_bounds__(256)
spmm_mid(int layer, int n_nodes) {
    int warp = (blockIdx.x * blockDim.x + threadIdx.x) >> 5;
    int lane = threadIdx.x & 31;
    if (warp >= n_nodes) return;

    const Half4* xin  = (layer == 1) ? g_y0 : g_y1;
    Half4*       xout = (layer == 1) ? g_y1 : g_y2;

    float dv = g_dinv[warp];
    float w2 = dv * dv;
    int start = __ldg(&g_rowptr[warp]);
    int end   = __ldg(&g_rowptr[warp + 1]);

    float a0 = 0.f, a1 = 0.f, a2 = 0.f, a3 = 0.f;
    gather_row(xin, start, end, lane, a0, a1, a2, a3);

    Half4 r;
    r.h01 = __floats2half2_rn(a0 * w2, a1 * w2);
    r.h23 = __floats2half2_rn(a2 * w2, a3 * w2);
    xout[(size_t)warp * 32 + lane] = r;
}

// layer 3: gather y2 -> x3 = dinv*sum; fuse out = (emb + x1 + x2 + x3)/4
// with x1 = rinv*y1, x2 = rinv*y2.
__global__ void __launch_bounds__(256)
spmm_last(const float* __restrict__ uw, const float* __restrict__ iw,
          int num_users, int n_nodes, float* __restrict__ out) {
    int warp = (blockIdx.x * blockDim.x + threadIdx.x) >> 5;
    int lane = threadIdx.x & 31;
    if (warp >= n_nodes) return;

    float dv = g_dinv[warp];
    float rv = g_rinv[warp];
    int start = __ldg(&g_rowptr[warp]);
    int end   = __ldg(&g_rowptr[warp + 1]);

    float a0 = 0.f, a1 = 0.f, a2 = 0.f, a3 = 0.f;
    gather_row(g_y2, start, end, lane, a0, a1, a2, a3);
    a0 *= dv; a1 *= dv; a2 *= dv; a3 *= dv;      // x3

    Half4 w1 = g_y1[(size_t)warp * 32 + lane];
    Half4 w2 = g_y2[(size_t)warp * 32 + lane];
    float2 p01 = __half22float2(w1.h01);
    float2 p23 = __half22float2(w1.h23);
    float2 q01 = __half22float2(w2.h01);
    float2 q23 = __half22float2(w2.h23);

    const float4* ep = (const float4*)((warp < num_users)
                          ? uw + (size_t)warp * D
                          : iw + (size_t)(warp - num_users) * D);
    float4 e = ep[lane];

    float4 o;
    o.x = (e.x + rv * (p01.x + q01.x) + a0) * 0.25f;
    o.y = (e.y + rv * (p01.y + q01.y) + a1) * 0.25f;
    o.z = (e.z + rv * (p23.x + q23.x) + a2) * 0.25f;
    o.w = (e.w + rv * (p23.y + q23.y) + a3) * 0.25f;
    ((float4*)(out + (size_t)warp * D))[lane] = o;
}

// --------------------------------------------------------------- launch ----

extern "C" void kernel_launch(void* const* d_in, const int* in_sizes, int n_in,
                              void* d_out, int out_size) {
    const float* uw = (const float*)d_in[0];
    const float* iw = (const float*)d_in[1];
    const int*   ei = (const int*)d_in[2];

    int num_users = in_sizes[0] / D;
    int num_items = in_sizes[1] / D;
    int n_nodes = num_users + num_items;
    int nE = in_sizes[2] / 2;
    const int* src = ei;
    const int* dst = ei + nE;
    float* out = (float*)d_out;

    // CSR build (g_deg arrives zeroed: module init / self-zero in scan23)
    hist_kernel<<<((nE + 3) / 4 + 255) / 256, 256>>>(src, nE);
    int nb = (n_nodes + SCAN_BLK - 1) / SCAN_BLK;
    scan1_kernel<<<nb, SCAN_BLK>>>(n_nodes);
    scan23_kernel<<<(n_nodes + 255) / 256, 256>>>(n_nodes, nb);

    int nscat = (nE + 3) / 4;
    int total_threads = nscat + n_nodes * 32;
    scatcvt_kernel<<<(total_threads + 255) / 256, 256>>>(uw, iw, src, dst, nE,
                                                         nscat, num_users, n_nodes);

    // 3 propagation layers
    int blocks = (n_nodes * 32 + 255) / 256;
    spmm_mid<<<blocks, 256>>>(1, n_nodes);
    spmm_mid<<<blocks, 256>>>(2, n_nodes);
    spmm_last<<<blocks, 256>>>(uw, iw, num_users, n_nodes, out);
}